// round 1
// baseline (speedup 1.0000x reference)
#include <cuda_runtime.h>
#include <cuda_bf16.h>
#include <float.h>

// ---------------- problem constants ----------------
#define BATCH      8
#define NPTS       1024
#define NPOINTS    (BATCH * NPTS)        // 8192
#define HEADC      8
#define SHAPEC     256
#define XCH        (HEADC + SHAPEC)      // 264
#define NEXPERT    16
#define SC_HID     256
#define SC_OUT     128
#define INTERC     (HEADC + SC_OUT)      // 136
#define C1OUT      256
#define C2OUT      512
#define C3OUT      1024
#define DEC1       1024
#define DEC2       2048
#define DEC3       8192
#define TILE_PTS   32
#define MAXTILES   (NPOINTS / TILE_PTS + NEXPERT)   // 272

// ---------------- scratch (device globals; no runtime alloc) ----------------
__device__ float g_xT[NPOINTS * SHAPEC];          // [B*N, 256] transposed shape features
__device__ float g_xi[BATCH * INTERC * NPTS];     // [B, 136, N]
__device__ float g_h1[BATCH * C1OUT * NPTS];      // [B, 256, N]
__device__ float g_h2[BATCH * C2OUT * NPTS];      // [B, 512, N]
__device__ float g_h3[BATCH * C3OUT * NPTS];      // [B, 1024, N]
__device__ float g_lat[BATCH * C3OUT];
__device__ float g_d1[BATCH * DEC1];
__device__ float g_d2[BATCH * DEC2];
__device__ int   g_idx[NPOINTS];
__device__ int   g_tileExpert[MAXTILES];
__device__ int   g_tileStart[MAXTILES];
__device__ int   g_tileLen[MAXTILES];
__device__ int   g_nTiles;

// ---------------- 1. transpose shape features: x[b,8+c,n] -> xT[(b*N+n)*256+c] ----
__global__ void k_transpose(const float* __restrict__ x) {
    __shared__ float t[32][33];
    int b  = blockIdx.z;
    int cB = blockIdx.x * 32;
    int nB = blockIdx.y * 32;
    int tx = threadIdx.x, ty = threadIdx.y;
    const float* xb = x + (size_t)b * XCH * NPTS;
#pragma unroll
    for (int i = ty; i < 32; i += 8)
        t[i][tx] = xb[(size_t)(HEADC + cB + i) * NPTS + nB + tx];
    __syncthreads();
    float* o = g_xT + ((size_t)b * NPTS + nB) * SHAPEC + cB;
#pragma unroll
    for (int i = ty; i < 32; i += 8)
        o[(size_t)i * SHAPEC + tx] = t[tx][i];
}

// ---------------- 2. copy head channels into xi ----------------
__global__ void k_head(const float* __restrict__ x) {
    int i = blockIdx.x * 256 + threadIdx.x;          // < 8*8*1024
    int b = i >> 13, rem = i & 8191;
    g_xi[(size_t)b * INTERC * NPTS + rem] = x[(size_t)b * XCH * NPTS + rem];
}

// ---------------- 3. counting sort points by category; build tile table ------
__global__ void k_build(const int* __restrict__ cats) {
    __shared__ int cnt[NEXPERT];
    __shared__ int off[NEXPERT + 1];
    __shared__ int cur[NEXPERT];
    int tid = threadIdx.x;
    if (tid < NEXPERT) cnt[tid] = 0;
    __syncthreads();
    for (int i = tid; i < NPOINTS; i += blockDim.x) atomicAdd(&cnt[cats[i]], 1);
    __syncthreads();
    if (tid == 0) {
        int s = 0;
        for (int e = 0; e < NEXPERT; e++) { off[e] = s; s += cnt[e]; }
        off[NEXPERT] = s;
        int t = 0;
        for (int e = 0; e < NEXPERT; e++)
            for (int st = off[e]; st < off[e + 1]; st += TILE_PTS) {
                g_tileExpert[t] = e;
                g_tileStart[t]  = st;
                g_tileLen[t]    = min(TILE_PTS, off[e + 1] - st);
                t++;
            }
        g_nTiles = t;
    }
    __syncthreads();
    if (tid < NEXPERT) cur[tid] = off[tid];
    __syncthreads();
    for (int i = tid; i < NPOINTS; i += blockDim.x) {
        int pos = atomicAdd(&cur[cats[i]], 1);
        g_idx[pos] = i;
    }
}

// ---------------- 4. expert shape MLP: 32 pts/block, one expert/block --------
// dynamic smem: sfs[32][256] + h[32][256] = 64 KB
__global__ void __launch_bounds__(256) k_expert(
    const float* __restrict__ W1, const float* __restrict__ b1,
    const float* __restrict__ W2, const float* __restrict__ b2)
{
    int t = blockIdx.x;
    if (t >= g_nTiles) return;
    int e = g_tileExpert[t], start = g_tileStart[t], len = g_tileLen[t];

    extern __shared__ float sm[];
    float* sfs = sm;                       // [32][256]
    float* hsh = sm + TILE_PTS * SC_HID;   // [32][256]
    __shared__ int pidx[TILE_PTS];

    int tid = threadIdx.x;
    if (tid < TILE_PTS) pidx[tid] = (tid < len) ? g_idx[start + tid] : -1;
    __syncthreads();

    // load 32 point rows (contiguous 256 floats each) into smem
    for (int i = tid; i < TILE_PTS * 64; i += 256) {
        int p = i >> 6, c4 = i & 63;
        float4 v = make_float4(0.f, 0.f, 0.f, 0.f);
        int pi = pidx[p];
        if (pi >= 0) v = ((const float4*)(g_xT + (size_t)pi * SHAPEC))[c4];
        ((float4*)(sfs + p * SHAPEC))[c4] = v;
    }
    __syncthreads();

    // stage 1: h = relu(sf @ W1[e] + b1[e]); thread = output channel (256)
    const float* w1 = W1 + (size_t)e * SHAPEC * SC_HID;
    float acc[TILE_PTS];
#pragma unroll
    for (int p = 0; p < TILE_PTS; p++) acc[p] = 0.f;
    for (int k = 0; k < SHAPEC; k += 4) {
        float wa = w1[(size_t)(k + 0) * SC_HID + tid];
        float wb = w1[(size_t)(k + 1) * SC_HID + tid];
        float wc = w1[(size_t)(k + 2) * SC_HID + tid];
        float wd = w1[(size_t)(k + 3) * SC_HID + tid];
#pragma unroll
        for (int p = 0; p < TILE_PTS; p++) {
            float4 s = ((const float4*)(sfs + p * SHAPEC))[k >> 2];
            acc[p] = fmaf(s.x, wa, acc[p]);
            acc[p] = fmaf(s.y, wb, acc[p]);
            acc[p] = fmaf(s.z, wc, acc[p]);
            acc[p] = fmaf(s.w, wd, acc[p]);
        }
    }
    float bias1 = b1[e * SC_HID + tid];
#pragma unroll
    for (int p = 0; p < TILE_PTS; p++)
        hsh[p * SC_HID + tid] = fmaxf(acc[p] + bias1, 0.f);
    __syncthreads();

    // stage 2: o = h @ W2[e] + b2[e]; threads: c = tid&127, half of points
    int c  = tid & 127;
    int ph = (tid >> 7) * 16;
    const float* w2 = W2 + (size_t)e * SC_HID * SC_OUT;
    float acc2[16];
#pragma unroll
    for (int p = 0; p < 16; p++) acc2[p] = 0.f;
    for (int k = 0; k < SC_HID; k += 4) {
        float wa = w2[(size_t)(k + 0) * SC_OUT + c];
        float wb = w2[(size_t)(k + 1) * SC_OUT + c];
        float wc = w2[(size_t)(k + 2) * SC_OUT + c];
        float wd = w2[(size_t)(k + 3) * SC_OUT + c];
#pragma unroll
        for (int p = 0; p < 16; p++) {
            float4 h4 = ((const float4*)(hsh + (ph + p) * SC_HID))[k >> 2];
            acc2[p] = fmaf(h4.x, wa, acc2[p]);
            acc2[p] = fmaf(h4.y, wb, acc2[p]);
            acc2[p] = fmaf(h4.z, wc, acc2[p]);
            acc2[p] = fmaf(h4.w, wd, acc2[p]);
        }
    }
    float bias2 = b2[e * SC_OUT + c];
#pragma unroll
    for (int p = 0; p < 16; p++) {
        int pi = pidx[ph + p];
        if (pi >= 0) {
            int b = pi >> 10, n = pi & 1023;
            g_xi[(size_t)b * INTERC * NPTS + (size_t)(HEADC + c) * NPTS + n] = acc2[p] + bias2;
        }
    }
}

// ---------------- 5. pointwise conv as SGEMM: C[b] = act(W @ X[b] + bias) ----
// W: [M,K] row-major; X: [B,K,1024]; C: [B,M,1024]. 128x128x8 tiles, 8x8/thread.
template <int RELU>
__global__ void __launch_bounds__(256) conv_gemm(
    const float* __restrict__ W, const float* __restrict__ X,
    const float* __restrict__ bias, float* __restrict__ C,
    int K, int M)
{
    const int N = NPTS;
    int b  = blockIdx.z;
    int n0 = blockIdx.x * 128;
    int m0 = blockIdx.y * 128;
    const float* Xb = X + (size_t)b * K * N;
    float* Cb = C + (size_t)b * M * N;

    __shared__ float As[8][128];
    __shared__ float Bs[8][128];

    int tid = threadIdx.x;
    int tx = tid & 15, ty = tid >> 4;

    float acc[8][8];
#pragma unroll
    for (int i = 0; i < 8; i++)
#pragma unroll
        for (int j = 0; j < 8; j++) acc[i][j] = 0.f;

    int arow = tid >> 1, akk = (tid & 1) * 4;
    int bkrw = tid >> 5, bcol = (tid & 31) * 4;

    for (int kb = 0; kb < K; kb += 8) {
        float4 av = *(const float4*)(W + (size_t)(m0 + arow) * K + kb + akk);
        As[akk + 0][arow] = av.x;
        As[akk + 1][arow] = av.y;
        As[akk + 2][arow] = av.z;
        As[akk + 3][arow] = av.w;
        float4 bv = *(const float4*)(Xb + (size_t)(kb + bkrw) * N + n0 + bcol);
        *(float4*)(&Bs[bkrw][bcol]) = bv;
        __syncthreads();
#pragma unroll
        for (int kk = 0; kk < 8; kk++) {
            float a[8], bb[8];
#pragma unroll
            for (int i = 0; i < 8; i++) a[i] = As[kk][ty * 8 + i];
#pragma unroll
            for (int j = 0; j < 8; j++) bb[j] = Bs[kk][tx * 8 + j];
#pragma unroll
            for (int i = 0; i < 8; i++)
#pragma unroll
                for (int j = 0; j < 8; j++)
                    acc[i][j] = fmaf(a[i], bb[j], acc[i][j]);
        }
        __syncthreads();
    }

#pragma unroll
    for (int i = 0; i < 8; i++) {
        int r = m0 + ty * 8 + i;
        float bs = bias[r];
        float v[8];
#pragma unroll
        for (int j = 0; j < 8; j++) {
            v[j] = acc[i][j] + bs;
            if (RELU) v[j] = fmaxf(v[j], 0.f);
        }
        float* dst = Cb + (size_t)r * N + n0 + tx * 8;
        *(float4*)(dst)     = make_float4(v[0], v[1], v[2], v[3]);
        *(float4*)(dst + 4) = make_float4(v[4], v[5], v[6], v[7]);
    }
}

// ---------------- 6. max pool over N ----------------
__global__ void k_pool(float* __restrict__ extra, int write_extra) {
    int row  = blockIdx.x * 8 + (threadIdx.x >> 5);   // < 8192
    int lane = threadIdx.x & 31;
    const float* r = g_h3 + (size_t)row * NPTS;
    float m = -FLT_MAX;
    for (int i = lane; i < NPTS; i += 32) m = fmaxf(m, r[i]);
#pragma unroll
    for (int o = 16; o; o >>= 1) m = fmaxf(m, __shfl_xor_sync(0xFFFFFFFFu, m, o));
    if (lane == 0) {
        g_lat[row] = m;
        if (write_extra) extra[row] = m;
    }
}

// ---------------- 7. decoder MLP: Out[8,N] = act(A[8,K] @ W[K,N] + bias) -----
// block = 64 cols x 4 k-slices; A staged in dynamic smem (8*K floats)
template <int RELU>
__global__ void __launch_bounds__(256) mlp8(
    const float* __restrict__ A, const float* __restrict__ W,
    const float* __restrict__ bias, float* __restrict__ Out,
    int K, int N)
{
    extern __shared__ float Ash[];          // [8][K]
    __shared__ float red[256 * 8];
    int tid = threadIdx.x;
    for (int i = tid; i < 8 * K / 4; i += 256)
        ((float4*)Ash)[i] = ((const float4*)A)[i];
    __syncthreads();

    int col   = blockIdx.x * 64 + (tid & 63);
    int slice = tid >> 6;
    int kPer  = K >> 2;
    int k0    = slice * kPer;

    float acc[8];
#pragma unroll
    for (int bb = 0; bb < 8; bb++) acc[bb] = 0.f;

    for (int k = k0; k < k0 + kPer; k += 4) {
        float w0 = W[(size_t)(k + 0) * N + col];
        float w1 = W[(size_t)(k + 1) * N + col];
        float w2 = W[(size_t)(k + 2) * N + col];
        float w3 = W[(size_t)(k + 3) * N + col];
#pragma unroll
        for (int bb = 0; bb < 8; bb++) {
            float4 a4 = ((const float4*)(Ash + bb * K))[k >> 2];
            acc[bb] = fmaf(a4.x, w0, acc[bb]);
            acc[bb] = fmaf(a4.y, w1, acc[bb]);
            acc[bb] = fmaf(a4.z, w2, acc[bb]);
            acc[bb] = fmaf(a4.w, w3, acc[bb]);
        }
    }
#pragma unroll
    for (int bb = 0; bb < 8; bb++) red[tid * 8 + bb] = acc[bb];
    __syncthreads();
    if (slice == 0) {
        float bsv = bias[col];
#pragma unroll
        for (int bb = 0; bb < 8; bb++) {
            float v = red[tid * 8 + bb] + red[(tid + 64) * 8 + bb]
                    + red[(tid + 128) * 8 + bb] + red[(tid + 192) * 8 + bb] + bsv;
            if (RELU) v = fmaxf(v, 0.f);
            Out[(size_t)bb * N + col] = v;
        }
    }
}

// ---------------- launch ----------------
extern "C" void kernel_launch(void* const* d_in, const int* in_sizes, int n_in,
                              void* d_out, int out_size) {
    const float* x    = (const float*)d_in[0];
    const int*   cats = (const int*)  d_in[1];
    const float* W1   = (const float*)d_in[2];
    const float* b1   = (const float*)d_in[3];
    const float* W2   = (const float*)d_in[4];
    const float* b2   = (const float*)d_in[5];
    const float* Wc1  = (const float*)d_in[6];
    const float* bc1  = (const float*)d_in[7];
    const float* Wc2  = (const float*)d_in[8];
    const float* bc2  = (const float*)d_in[9];
    const float* Wc3  = (const float*)d_in[10];
    const float* bc3  = (const float*)d_in[11];
    const float* Wd1  = (const float*)d_in[12];
    const float* bd1  = (const float*)d_in[13];
    const float* Wd2  = (const float*)d_in[14];
    const float* bd2  = (const float*)d_in[15];
    const float* Wd3  = (const float*)d_in[16];
    const float* bd3  = (const float*)d_in[17];
    float* out = (float*)d_out;

    cudaFuncSetAttribute(k_expert, cudaFuncAttributeMaxDynamicSharedMemorySize, 65536);
    cudaFuncSetAttribute(mlp8<1>,  cudaFuncAttributeMaxDynamicSharedMemorySize, 65536);
    cudaFuncSetAttribute(mlp8<0>,  cudaFuncAttributeMaxDynamicSharedMemorySize, 65536);

    // device symbol addresses resolved at runtime for scratch buffers
    float *p_xi, *p_h1, *p_h2, *p_h3, *p_lat, *p_d1, *p_d2;
    cudaGetSymbolAddress((void**)&p_xi,  g_xi);
    cudaGetSymbolAddress((void**)&p_h1,  g_h1);
    cudaGetSymbolAddress((void**)&p_h2,  g_h2);
    cudaGetSymbolAddress((void**)&p_h3,  g_h3);
    cudaGetSymbolAddress((void**)&p_lat, g_lat);
    cudaGetSymbolAddress((void**)&p_d1,  g_d1);
    cudaGetSymbolAddress((void**)&p_d2,  g_d2);

    // 1-2: feature transpose + head copy
    k_transpose<<<dim3(SHAPEC / 32, NPTS / 32, BATCH), dim3(32, 8)>>>(x);
    k_head<<<(BATCH * HEADC * NPTS) / 256, 256>>>(x);

    // 3-4: expert routing + per-point shape MLP
    k_build<<<1, 256>>>(cats);
    k_expert<<<MAXTILES, 256, 65536>>>(W1, b1, W2, b2);

    // 5: conv stack
    conv_gemm<1><<<dim3(NPTS / 128, C1OUT / 128, BATCH), 256>>>(Wc1, p_xi, bc1, p_h1, INTERC, C1OUT);
    conv_gemm<1><<<dim3(NPTS / 128, C2OUT / 128, BATCH), 256>>>(Wc2, p_h1, bc2, p_h2, C1OUT, C2OUT);
    conv_gemm<0><<<dim3(NPTS / 128, C3OUT / 128, BATCH), 256>>>(Wc3, p_h2, bc3, p_h3, C2OUT, C3OUT);

    // 6: max pool (also writes latent to output tail if requested)
    int write_extra = (out_size >= 65536 + 8192) ? 1 : 0;
    k_pool<<<(BATCH * C3OUT) / 8, 256>>>(out + 65536, write_extra);

    // 7: decoder MLP
    mlp8<1><<<DEC1 / 64, 256, 8 * DEC1 * 4>>>(p_lat, Wd1, bd1, p_d1, DEC1, DEC1);
    mlp8<1><<<DEC2 / 64, 256, 8 * DEC1 * 4>>>(p_d1,  Wd2, bd2, p_d2, DEC1, DEC2);
    mlp8<0><<<DEC3 / 64, 256, 8 * DEC2 * 4>>>(p_d2,  Wd3, bd3, out,  DEC2, DEC3);
}

// round 3
// speedup vs baseline: 1.3828x; 1.3828x over previous
#include <cuda_runtime.h>
#include <cuda_bf16.h>
#include <float.h>
#include <stdint.h>

// ---------------- problem constants ----------------
#define BATCH      8
#define NPTS       1024
#define NPOINTS    (BATCH * NPTS)        // 8192
#define HEADC      8
#define SHAPEC     256
#define XCH        (HEADC + SHAPEC)      // 264
#define NEXPERT    16
#define SC_HID     256
#define SC_OUT     128
#define K0PAD      160                   // 136 padded to 160
#define C1OUT      256
#define C2OUT      512
#define C3OUT      1024
#define DEC1       1024
#define DEC2       2048
#define DEC3       8192
#define TILE_PTS   32
#define MAXTILES   (NPOINTS / TILE_PTS + NEXPERT)   // 272

typedef __nv_bfloat16 bf16;

// ---------------- scratch (device globals; no runtime alloc) ----------------
__device__ float g_xT[NPOINTS * SHAPEC];                    // [8192,256] point-major
__device__ __align__(256) bf16 g_a0hi[NPOINTS * K0PAD];
__device__ __align__(256) bf16 g_a0lo[NPOINTS * K0PAD];
__device__ __align__(256) bf16 g_a1hi[NPOINTS * C1OUT];
__device__ __align__(256) bf16 g_a1lo[NPOINTS * C1OUT];
__device__ __align__(256) bf16 g_a2hi[NPOINTS * C2OUT];
__device__ __align__(256) bf16 g_a2lo[NPOINTS * C2OUT];
__device__ float g_h3[NPOINTS * C3OUT];                     // [8192,1024] point-major
__device__ __align__(256) bf16 g_w1hi[C1OUT * K0PAD];
__device__ __align__(256) bf16 g_w1lo[C1OUT * K0PAD];
__device__ __align__(256) bf16 g_w2hi[C2OUT * C1OUT];
__device__ __align__(256) bf16 g_w2lo[C2OUT * C1OUT];
__device__ __align__(256) bf16 g_w3hi[C3OUT * C2OUT];
__device__ __align__(256) bf16 g_w3lo[C3OUT * C2OUT];
__device__ float g_part[BATCH * 8 * C3OUT];
__device__ float g_lat[BATCH * C3OUT];
__device__ float g_d1[BATCH * DEC1];
__device__ float g_d2[BATCH * DEC2];
__device__ int   g_idx[NPOINTS];
__device__ int   g_tileExpert[MAXTILES];
__device__ int   g_tileStart[MAXTILES];
__device__ int   g_tileLen[MAXTILES];
__device__ int   g_nTiles;

// ---------------- ptx helpers (all sm_80-safe, no arch-'a' gating) ----------
__device__ __forceinline__ uint32_t smem_u32(const void* p) {
    uint32_t a;
    asm("{ .reg .u64 t; cvta.to.shared.u64 t, %1; cvt.u32.u64 %0, t; }" : "=r"(a) : "l"(p));
    return a;
}
#define CP_ASYNC16(dst, src) \
    asm volatile("cp.async.cg.shared.global [%0], [%1], 16;" :: "r"(dst), "l"(src))
#define CP_COMMIT() asm volatile("cp.async.commit_group;" ::: "memory")
#define CP_WAIT0()  asm volatile("cp.async.wait_group 0;" ::: "memory")
#define CP_WAIT1()  asm volatile("cp.async.wait_group 1;" ::: "memory")

#define LDSM4(r, addr) \
    asm volatile("ldmatrix.sync.aligned.m8n8.x4.shared.b16 {%0,%1,%2,%3}, [%4];" \
        : "=r"((r)[0]), "=r"((r)[1]), "=r"((r)[2]), "=r"((r)[3]) : "r"(addr))

__device__ __forceinline__ void mma_bf16(float* d, const uint32_t* a,
                                         uint32_t b0, uint32_t b1) {
    asm volatile(
        "mma.sync.aligned.m16n8k16.row.col.f32.bf16.bf16.f32 "
        "{%0,%1,%2,%3}, {%4,%5,%6,%7}, {%8,%9}, {%0,%1,%2,%3};"
        : "+f"(d[0]), "+f"(d[1]), "+f"(d[2]), "+f"(d[3])
        : "r"(a[0]), "r"(a[1]), "r"(a[2]), "r"(a[3]), "r"(b0), "r"(b1));
}

__device__ __forceinline__ void bf16_split(float v, bf16& h, bf16& l) {
    h = __float2bfloat16(v);
    l = __float2bfloat16(v - __bfloat162float(h));
}

// ---------------- 1. transpose shape features into point-major g_xT ----------
__global__ void k_transpose(const float* __restrict__ x) {
    __shared__ float t[32][33];
    int b  = blockIdx.z;
    int cB = blockIdx.x * 32;
    int nB = blockIdx.y * 32;
    int tx = threadIdx.x, ty = threadIdx.y;
    const float* xb = x + (size_t)b * XCH * NPTS;
#pragma unroll
    for (int i = ty; i < 32; i += 8)
        t[i][tx] = xb[(size_t)(HEADC + cB + i) * NPTS + nB + tx];
    __syncthreads();
    float* o = g_xT + ((size_t)b * NPTS + nB) * SHAPEC + cB;
#pragma unroll
    for (int i = ty; i < 32; i += 8)
        o[(size_t)i * SHAPEC + tx] = t[tx][i];
}

// ---------------- 2. head channels + zero pad into a0 (bf16 hi/lo) ----------
__global__ void k_head(const float* __restrict__ x) {
    int i = blockIdx.x * 256 + threadIdx.x;     // 8192 * 32
    int p = i >> 5, s = i & 31;
    float v = 0.f;
    int col;
    if (s < 8) {
        int b = p >> 10, n = p & 1023;
        v = x[(size_t)b * XCH * NPTS + (size_t)s * NPTS + n];
        col = s;
    } else {
        col = 128 + s;                           // 136..159 pad
    }
    bf16 h, l; bf16_split(v, h, l);
    g_a0hi[(size_t)p * K0PAD + col] = h;
    g_a0lo[(size_t)p * K0PAD + col] = l;
}

// ---------------- 3. weight split+pad: W[C,Kin] -> bf16 hi/lo [C,Kpad] -------
__global__ void k_wsplit(const float* __restrict__ w, bf16* __restrict__ hi,
                         bf16* __restrict__ lo, int Kin, int Kpad, int total) {
    int i = blockIdx.x * 256 + threadIdx.x;
    if (i >= total) return;
    int c = i / Kpad, k = i - c * Kpad;
    float v = (k < Kin) ? w[(size_t)c * Kin + k] : 0.f;
    bf16 h, l; bf16_split(v, h, l);
    hi[i] = h;
    lo[i] = l;
}

// ---------------- 4. counting sort points by category ------------------------
__global__ void k_build(const int* __restrict__ cats) {
    __shared__ int cnt[NEXPERT];
    __shared__ int off[NEXPERT + 1];
    __shared__ int cur[NEXPERT];
    int tid = threadIdx.x;
    if (tid < NEXPERT) cnt[tid] = 0;
    __syncthreads();
    for (int i = tid; i < NPOINTS; i += blockDim.x) atomicAdd(&cnt[cats[i]], 1);
    __syncthreads();
    if (tid == 0) {
        int s = 0;
        for (int e = 0; e < NEXPERT; e++) { off[e] = s; s += cnt[e]; }
        off[NEXPERT] = s;
        int t = 0;
        for (int e = 0; e < NEXPERT; e++)
            for (int st = off[e]; st < off[e + 1]; st += TILE_PTS) {
                g_tileExpert[t] = e;
                g_tileStart[t]  = st;
                g_tileLen[t]    = min(TILE_PTS, off[e + 1] - st);
                t++;
            }
        g_nTiles = t;
    }
    __syncthreads();
    if (tid < NEXPERT) cur[tid] = off[tid];
    __syncthreads();
    for (int i = tid; i < NPOINTS; i += blockDim.x) {
        int pos = atomicAdd(&cur[cats[i]], 1);
        g_idx[pos] = i;
    }
}

// ---------------- 5. expert shape MLP (fp32 compute, bf16-split output) ------
__global__ void __launch_bounds__(256) k_expert(
    const float* __restrict__ W1, const float* __restrict__ b1,
    const float* __restrict__ W2, const float* __restrict__ b2)
{
    int t = blockIdx.x;
    if (t >= g_nTiles) return;
    int e = g_tileExpert[t], start = g_tileStart[t], len = g_tileLen[t];

    extern __shared__ float sm[];
    float* sfs = sm;                       // [32][256]
    float* hsh = sm + TILE_PTS * SC_HID;   // [32][256]
    __shared__ int pidx[TILE_PTS];

    int tid = threadIdx.x;
    if (tid < TILE_PTS) pidx[tid] = (tid < len) ? g_idx[start + tid] : -1;
    __syncthreads();

    for (int i = tid; i < TILE_PTS * 64; i += 256) {
        int p = i >> 6, c4 = i & 63;
        float4 v = make_float4(0.f, 0.f, 0.f, 0.f);
        int pi = pidx[p];
        if (pi >= 0) v = ((const float4*)(g_xT + (size_t)pi * SHAPEC))[c4];
        ((float4*)(sfs + p * SHAPEC))[c4] = v;
    }
    __syncthreads();

    const float* w1 = W1 + (size_t)e * SHAPEC * SC_HID;
    float acc[TILE_PTS];
#pragma unroll
    for (int p = 0; p < TILE_PTS; p++) acc[p] = 0.f;
    for (int k = 0; k < SHAPEC; k += 4) {
        float wa = w1[(size_t)(k + 0) * SC_HID + tid];
        float wb = w1[(size_t)(k + 1) * SC_HID + tid];
        float wc = w1[(size_t)(k + 2) * SC_HID + tid];
        float wd = w1[(size_t)(k + 3) * SC_HID + tid];
#pragma unroll
        for (int p = 0; p < TILE_PTS; p++) {
            float4 s = ((const float4*)(sfs + p * SHAPEC))[k >> 2];
            acc[p] = fmaf(s.x, wa, acc[p]);
            acc[p] = fmaf(s.y, wb, acc[p]);
            acc[p] = fmaf(s.z, wc, acc[p]);
            acc[p] = fmaf(s.w, wd, acc[p]);
        }
    }
    float bias1 = b1[e * SC_HID + tid];
#pragma unroll
    for (int p = 0; p < TILE_PTS; p++)
        hsh[p * SC_HID + tid] = fmaxf(acc[p] + bias1, 0.f);
    __syncthreads();

    int c  = tid & 127;
    int ph = (tid >> 7) * 16;
    const float* w2 = W2 + (size_t)e * SC_HID * SC_OUT;
    float acc2[16];
#pragma unroll
    for (int p = 0; p < 16; p++) acc2[p] = 0.f;
    for (int k = 0; k < SC_HID; k += 4) {
        float wa = w2[(size_t)(k + 0) * SC_OUT + c];
        float wb = w2[(size_t)(k + 1) * SC_OUT + c];
        float wc = w2[(size_t)(k + 2) * SC_OUT + c];
        float wd = w2[(size_t)(k + 3) * SC_OUT + c];
#pragma unroll
        for (int p = 0; p < 16; p++) {
            float4 h4 = ((const float4*)(hsh + (ph + p) * SC_HID))[k >> 2];
            acc2[p] = fmaf(h4.x, wa, acc2[p]);
            acc2[p] = fmaf(h4.y, wb, acc2[p]);
            acc2[p] = fmaf(h4.z, wc, acc2[p]);
            acc2[p] = fmaf(h4.w, wd, acc2[p]);
        }
    }
    float bias2 = b2[e * SC_OUT + c];
#pragma unroll
    for (int p = 0; p < 16; p++) {
        int pi = pidx[ph + p];
        if (pi >= 0) {
            float v = acc2[p] + bias2;
            bf16 h, l; bf16_split(v, h, l);
            g_a0hi[(size_t)pi * K0PAD + HEADC + c] = h;
            g_a0lo[(size_t)pi * K0PAD + HEADC + c] = l;
        }
    }
}

// ---------------- 6. bf16 mma.sync GEMM (3-MMA hi/lo split) ----------------
// D[128 pts, 128 ch] per CTA = A[pts,K] @ W[ch,K]^T, both K-major bf16.
// K slab = 32 bf16, rows padded to 80B in smem (conflict-free ldmatrix).
// smem blocks per stage: AH(10240) AL BH BL -> 40960B/stage, 2 stages.
#define GSMEM (2 * 40960)

template <int KTOT, int RELU, int SPLIT>
__global__ void __launch_bounds__(256) gemm_mma(
    const bf16* __restrict__ aHi, const bf16* __restrict__ aLo,
    const bf16* __restrict__ wHi, const bf16* __restrict__ wLo,
    const float* __restrict__ bias,
    bf16* __restrict__ oHi, bf16* __restrict__ oLo,
    float* __restrict__ oF, int KOUT)
{
    extern __shared__ char smraw[];
    const int NK = KTOT / 32;
    int tid = threadIdx.x, lane = tid & 31, wid = tid >> 5;
    int warp_m = wid & 1, warp_n = wid >> 1;     // 2 x 4 warps
    int m0 = blockIdx.x * 128, c0 = blockIdx.y * 128;

    uint32_t smBase = smem_u32(smraw);
    // ldmatrix per-lane offsets (bytes) within an operand block
    uint32_t rowA = (uint32_t)(warp_m * 64 + (lane & 15)) * 80 + (lane >> 4) * 16;
    uint32_t rowB = (uint32_t)(warp_n * 32 + (lane & 15)) * 80 + (lane >> 4) * 16;

    float acc[4][4][4];
#pragma unroll
    for (int a = 0; a < 4; a++)
#pragma unroll
        for (int b = 0; b < 4; b++)
#pragma unroll
            for (int c = 0; c < 4; c++) acc[a][b][c] = 0.f;

    // ---- stage loader: 2048 x 16B chunks, 8 per thread ----
    auto loadStage = [&](int ks, int st) {
        uint32_t sb = smBase + st * 40960;
#pragma unroll
        for (int i = 0; i < 8; i++) {
            const int blk = i >> 1;                       // 0:AH 1:AL 2:BH 3:BL
            int id = tid + (i & 1) * 256;                 // 0..511
            int r = id >> 2, ch = id & 3;
            const bf16* src;
            if (blk == 0)      src = aHi + (size_t)(m0 + r) * KTOT;
            else if (blk == 1) src = aLo + (size_t)(m0 + r) * KTOT;
            else if (blk == 2) src = wHi + (size_t)(c0 + r) * KTOT;
            else               src = wLo + (size_t)(c0 + r) * KTOT;
            src += ks * 32 + ch * 8;
            uint32_t dst = sb + blk * 10240 + (uint32_t)r * 80 + ch * 16;
            CP_ASYNC16(dst, src);
        }
        CP_COMMIT();
    };

    loadStage(0, 0);
    for (int ks = 0; ks < NK; ks++) {
        if (ks + 1 < NK) { loadStage(ks + 1, (ks + 1) & 1); CP_WAIT1(); }
        else             { CP_WAIT0(); }
        __syncthreads();

        uint32_t sb = smBase + (ks & 1) * 40960;
#pragma unroll
        for (int s = 0; s < 2; s++) {                     // two k16 steps
            uint32_t aH[4][4], aL[4][4], bH[2][4], bL[2][4];
#pragma unroll
            for (int mf = 0; mf < 4; mf++) {
                uint32_t ad = sb + rowA + (uint32_t)mf * (16 * 80) + s * 32;
                LDSM4(aH[mf], ad);
                LDSM4(aL[mf], ad + 10240);
            }
#pragma unroll
            for (int p = 0; p < 2; p++) {
                uint32_t bd = sb + 20480 + rowB + (uint32_t)p * (16 * 80) + s * 32;
                LDSM4(bH[p], bd);
                LDSM4(bL[p], bd + 10240);
            }
#pragma unroll
            for (int mf = 0; mf < 4; mf++)
#pragma unroll
                for (int nf = 0; nf < 4; nf++) {
                    int p = nf >> 1, sel = nf & 1;
                    uint32_t bh0 = bH[p][sel], bh1 = bH[p][sel + 2];
                    uint32_t bl0 = bL[p][sel], bl1 = bL[p][sel + 2];
                    mma_bf16(acc[mf][nf], aH[mf], bh0, bh1);
                    mma_bf16(acc[mf][nf], aH[mf], bl0, bl1);
                    mma_bf16(acc[mf][nf], aL[mf], bh0, bh1);
                }
        }
        __syncthreads();
    }

    // ---- epilogue: +bias, relu, bf16-split or f32 store ----
#pragma unroll
    for (int mf = 0; mf < 4; mf++) {
        int row = m0 + warp_m * 64 + mf * 16 + (lane >> 2);
#pragma unroll
        for (int nf = 0; nf < 4; nf++) {
            int col = c0 + warp_n * 32 + nf * 8 + 2 * (lane & 3);
            float b0v = bias[col], b1v = bias[col + 1];
            float v0 = acc[mf][nf][0] + b0v, v1 = acc[mf][nf][1] + b1v;
            float v2 = acc[mf][nf][2] + b0v, v3 = acc[mf][nf][3] + b1v;
            if (RELU) {
                v0 = fmaxf(v0, 0.f); v1 = fmaxf(v1, 0.f);
                v2 = fmaxf(v2, 0.f); v3 = fmaxf(v3, 0.f);
            }
            if (SPLIT) {
                bf16 h0, l0, h1, l1;
                bf16_split(v0, h0, l0); bf16_split(v1, h1, l1);
                __nv_bfloat162 hp; hp.x = h0; hp.y = h1;
                __nv_bfloat162 lp; lp.x = l0; lp.y = l1;
                *(__nv_bfloat162*)(oHi + (size_t)row * KOUT + col) = hp;
                *(__nv_bfloat162*)(oLo + (size_t)row * KOUT + col) = lp;
                bf16_split(v2, h0, l0); bf16_split(v3, h1, l1);
                hp.x = h0; hp.y = h1; lp.x = l0; lp.y = l1;
                *(__nv_bfloat162*)(oHi + (size_t)(row + 8) * KOUT + col) = hp;
                *(__nv_bfloat162*)(oLo + (size_t)(row + 8) * KOUT + col) = lp;
            } else {
                *(float2*)(oF + (size_t)row * KOUT + col) = make_float2(v0, v1);
                *(float2*)(oF + (size_t)(row + 8) * KOUT + col) = make_float2(v2, v3);
            }
        }
    }
}

// ---------------- 7. max pool (two-stage, point-major h3) ----------------
__global__ void k_poolA() {
    int b = blockIdx.x, ch = blockIdx.y, part = blockIdx.z;
    int c = ch * 256 + threadIdx.x;
    const float* base = g_h3 + ((size_t)(b * NPTS + part * 128)) * C3OUT + c;
    float m = -FLT_MAX;
#pragma unroll 8
    for (int n = 0; n < 128; n++) m = fmaxf(m, base[(size_t)n * C3OUT]);
    g_part[(b * 8 + part) * C3OUT + c] = m;
}
__global__ void k_poolB(float* __restrict__ extra, int we) {
    int i = blockIdx.x * 256 + threadIdx.x;   // 8192
    float m = -FLT_MAX;
    int b = i >> 10, c = i & 1023;
#pragma unroll
    for (int part = 0; part < 8; part++)
        m = fmaxf(m, g_part[(b * 8 + part) * C3OUT + c]);
    g_lat[i] = m;
    if (we) extra[i] = m;
}

// ---------------- 8. decoder MLP ----------------
template <int RELU>
__global__ void __launch_bounds__(256) mlp8(
    const float* __restrict__ A, const float* __restrict__ W,
    const float* __restrict__ bias, float* __restrict__ Out,
    int K, int N)
{
    extern __shared__ float Ash[];
    __shared__ float red[256 * 8];
    int tid = threadIdx.x;
    for (int i = tid; i < 8 * K / 4; i += 256)
        ((float4*)Ash)[i] = ((const float4*)A)[i];
    __syncthreads();

    int col   = blockIdx.x * 64 + (tid & 63);
    int slice = tid >> 6;
    int kPer  = K >> 2;
    int k0    = slice * kPer;

    float acc[8];
#pragma unroll
    for (int bb = 0; bb < 8; bb++) acc[bb] = 0.f;

    for (int k = k0; k < k0 + kPer; k += 4) {
        float w0 = W[(size_t)(k + 0) * N + col];
        float w1 = W[(size_t)(k + 1) * N + col];
        float w2 = W[(size_t)(k + 2) * N + col];
        float w3 = W[(size_t)(k + 3) * N + col];
#pragma unroll
        for (int bb = 0; bb < 8; bb++) {
            float4 a4 = ((const float4*)(Ash + bb * K))[k >> 2];
            acc[bb] = fmaf(a4.x, w0, acc[bb]);
            acc[bb] = fmaf(a4.y, w1, acc[bb]);
            acc[bb] = fmaf(a4.z, w2, acc[bb]);
            acc[bb] = fmaf(a4.w, w3, acc[bb]);
        }
    }
#pragma unroll
    for (int bb = 0; bb < 8; bb++) red[tid * 8 + bb] = acc[bb];
    __syncthreads();
    if (slice == 0) {
        float bsv = bias[col];
#pragma unroll
        for (int bb = 0; bb < 8; bb++) {
            float v = red[tid * 8 + bb] + red[(tid + 64) * 8 + bb]
                    + red[(tid + 128) * 8 + bb] + red[(tid + 192) * 8 + bb] + bsv;
            if (RELU) v = fmaxf(v, 0.f);
            Out[(size_t)bb * N + col] = v;
        }
    }
}

// ---------------- launch ----------------
extern "C" void kernel_launch(void* const* d_in, const int* in_sizes, int n_in,
                              void* d_out, int out_size) {
    const float* x    = (const float*)d_in[0];
    const int*   cats = (const int*)  d_in[1];
    const float* W1   = (const float*)d_in[2];
    const float* b1   = (const float*)d_in[3];
    const float* W2   = (const float*)d_in[4];
    const float* b2   = (const float*)d_in[5];
    const float* Wc1  = (const float*)d_in[6];
    const float* bc1  = (const float*)d_in[7];
    const float* Wc2  = (const float*)d_in[8];
    const float* bc2  = (const float*)d_in[9];
    const float* Wc3  = (const float*)d_in[10];
    const float* bc3  = (const float*)d_in[11];
    const float* Wd1  = (const float*)d_in[12];
    const float* bd1  = (const float*)d_in[13];
    const float* Wd2  = (const float*)d_in[14];
    const float* bd2  = (const float*)d_in[15];
    const float* Wd3  = (const float*)d_in[16];
    const float* bd3  = (const float*)d_in[17];
    float* out = (float*)d_out;

    cudaFuncSetAttribute(k_expert, cudaFuncAttributeMaxDynamicSharedMemorySize, 65536);
    cudaFuncSetAttribute(mlp8<1>,  cudaFuncAttributeMaxDynamicSharedMemorySize, 65536);
    cudaFuncSetAttribute(mlp8<0>,  cudaFuncAttributeMaxDynamicSharedMemorySize, 65536);
    cudaFuncSetAttribute(gemm_mma<K0PAD, 1, 1>, cudaFuncAttributeMaxDynamicSharedMemorySize, GSMEM);
    cudaFuncSetAttribute(gemm_mma<C1OUT, 1, 1>, cudaFuncAttributeMaxDynamicSharedMemorySize, GSMEM);
    cudaFuncSetAttribute(gemm_mma<C2OUT, 0, 0>, cudaFuncAttributeMaxDynamicSharedMemorySize, GSMEM);

    bf16 *p_a0h, *p_a0l, *p_a1h, *p_a1l, *p_a2h, *p_a2l;
    bf16 *p_w1h, *p_w1l, *p_w2h, *p_w2l, *p_w3h, *p_w3l;
    float *p_h3, *p_lat, *p_d1, *p_d2;
    cudaGetSymbolAddress((void**)&p_a0h, g_a0hi);
    cudaGetSymbolAddress((void**)&p_a0l, g_a0lo);
    cudaGetSymbolAddress((void**)&p_a1h, g_a1hi);
    cudaGetSymbolAddress((void**)&p_a1l, g_a1lo);
    cudaGetSymbolAddress((void**)&p_a2h, g_a2hi);
    cudaGetSymbolAddress((void**)&p_a2l, g_a2lo);
    cudaGetSymbolAddress((void**)&p_h3,  g_h3);
    cudaGetSymbolAddress((void**)&p_w1h, g_w1hi);
    cudaGetSymbolAddress((void**)&p_w1l, g_w1lo);
    cudaGetSymbolAddress((void**)&p_w2h, g_w2hi);
    cudaGetSymbolAddress((void**)&p_w2l, g_w2lo);
    cudaGetSymbolAddress((void**)&p_w3h, g_w3hi);
    cudaGetSymbolAddress((void**)&p_w3l, g_w3lo);
    cudaGetSymbolAddress((void**)&p_lat, g_lat);
    cudaGetSymbolAddress((void**)&p_d1,  g_d1);
    cudaGetSymbolAddress((void**)&p_d2,  g_d2);

    // feature prep
    k_transpose<<<dim3(SHAPEC / 32, NPTS / 32, BATCH), dim3(32, 8)>>>(x);
    k_head<<<(NPOINTS * 32) / 256, 256>>>(x);
    k_wsplit<<<(C1OUT * K0PAD + 255) / 256, 256>>>(Wc1, p_w1h, p_w1l, 136, K0PAD, C1OUT * K0PAD);
    k_wsplit<<<(C2OUT * C1OUT + 255) / 256, 256>>>(Wc2, p_w2h, p_w2l, C1OUT, C1OUT, C2OUT * C1OUT);
    k_wsplit<<<(C3OUT * C2OUT + 255) / 256, 256>>>(Wc3, p_w3h, p_w3l, C2OUT, C2OUT, C3OUT * C2OUT);

    // expert routing + per-point shape MLP
    k_build<<<1, 256>>>(cats);
    k_expert<<<MAXTILES, 256, 65536>>>(W1, b1, W2, b2);

    // conv stack on tensor cores (mma.sync bf16 split; batches folded)
    gemm_mma<K0PAD, 1, 1><<<dim3(64, C1OUT / 128), 256, GSMEM>>>(
        p_a0h, p_a0l, p_w1h, p_w1l, bc1, p_a1h, p_a1l, (float*)0, C1OUT);
    gemm_mma<C1OUT, 1, 1><<<dim3(64, C2OUT / 128), 256, GSMEM>>>(
        p_a1h, p_a1l, p_w2h, p_w2l, bc2, p_a2h, p_a2l, (float*)0, C2OUT);
    gemm_mma<C2OUT, 0, 0><<<dim3(64, C3OUT / 128), 256, GSMEM>>>(
        p_a2h, p_a2l, p_w3h, p_w3l, bc3, (bf16*)0, (bf16*)0, p_h3, C3OUT);

    // max pool
    int write_extra = (out_size >= 65536 + 8192) ? 1 : 0;
    k_poolA<<<dim3(BATCH, 4, 8), 256>>>();
    k_poolB<<<NPOINTS / 256, 256>>>(out + 65536, write_extra);

    // decoder MLP
    mlp8<1><<<DEC1 / 64, 256, 8 * DEC1 * 4>>>(p_lat, Wd1, bd1, p_d1, DEC1, DEC1);
    mlp8<1><<<DEC2 / 64, 256, 8 * DEC1 * 4>>>(p_d1,  Wd2, bd2, p_d2, DEC1, DEC2);
    mlp8<0><<<DEC3 / 64, 256, 8 * DEC2 * 4>>>(p_d2,  Wd3, bd3, out,  DEC2, DEC3);
}

// round 4
// speedup vs baseline: 1.5846x; 1.1459x over previous
#include <cuda_runtime.h>
#include <cuda_bf16.h>
#include <float.h>
#include <stdint.h>

// ---------------- problem constants ----------------
#define BATCH      8
#define NPTS       1024
#define NPOINTS    (BATCH * NPTS)        // 8192
#define HEADC      8
#define SHAPEC     256
#define XCH        (HEADC + SHAPEC)      // 264
#define NEXPERT    16
#define SC_HID     256
#define SC_OUT     128
#define K0PAD      160                   // 136 padded to 160
#define C1OUT      256
#define C2OUT      512
#define C3OUT      1024
#define DEC1       1024
#define DEC2       2048
#define DEC3       8192
#define ETILE      64
#define MAXTILES   (NPOINTS / ETILE + NEXPERT)   // 144

typedef __nv_bfloat16 bf16;

// ---------------- scratch (device globals; no runtime alloc) ----------------
__device__ __align__(256) bf16 g_xhi[NPOINTS * SHAPEC];   // [8192,256] point-major
__device__ __align__(256) bf16 g_xlo[NPOINTS * SHAPEC];
__device__ __align__(256) bf16 g_a0hi[NPOINTS * K0PAD];
__device__ __align__(256) bf16 g_a0lo[NPOINTS * K0PAD];
__device__ __align__(256) bf16 g_a1hi[NPOINTS * C1OUT];
__device__ __align__(256) bf16 g_a1lo[NPOINTS * C1OUT];
__device__ __align__(256) bf16 g_a2hi[NPOINTS * C2OUT];
__device__ __align__(256) bf16 g_a2lo[NPOINTS * C2OUT];
__device__ __align__(256) bf16 g_w1hi[C1OUT * K0PAD];
__device__ __align__(256) bf16 g_w1lo[C1OUT * K0PAD];
__device__ __align__(256) bf16 g_w2hi[C2OUT * C1OUT];
__device__ __align__(256) bf16 g_w2lo[C2OUT * C1OUT];
__device__ __align__(256) bf16 g_w3hi[C3OUT * C2OUT];
__device__ __align__(256) bf16 g_w3lo[C3OUT * C2OUT];
// expert weights transposed to [e][out][k], bf16 hi/lo
__device__ __align__(256) bf16 g_e1hi[NEXPERT * SC_HID * SHAPEC];
__device__ __align__(256) bf16 g_e1lo[NEXPERT * SC_HID * SHAPEC];
__device__ __align__(256) bf16 g_e2hi[NEXPERT * SC_OUT * SC_HID];
__device__ __align__(256) bf16 g_e2lo[NEXPERT * SC_OUT * SC_HID];
__device__ float g_part[BATCH * 8 * C3OUT];
__device__ float g_lat[BATCH * C3OUT];
__device__ float g_d1[BATCH * DEC1];
__device__ float g_d2[BATCH * DEC2];
__device__ int   g_idx[NPOINTS];
__device__ int   g_tileExpert[MAXTILES];
__device__ int   g_tileStart[MAXTILES];
__device__ int   g_tileLen[MAXTILES];
__device__ int   g_nTiles;

// ---------------- ptx helpers (sm_80-safe) ----------------
__device__ __forceinline__ uint32_t smem_u32(const void* p) {
    uint32_t a;
    asm("{ .reg .u64 t; cvta.to.shared.u64 t, %1; cvt.u32.u64 %0, t; }" : "=r"(a) : "l"(p));
    return a;
}
#define CP_ASYNC16(dst, src) \
    asm volatile("cp.async.cg.shared.global [%0], [%1], 16;" :: "r"(dst), "l"(src))
#define CP_COMMIT() asm volatile("cp.async.commit_group;" ::: "memory")
#define CP_WAIT0()  asm volatile("cp.async.wait_group 0;" ::: "memory")
#define CP_WAIT1()  asm volatile("cp.async.wait_group 1;" ::: "memory")

#define LDSM4(r, addr) \
    asm volatile("ldmatrix.sync.aligned.m8n8.x4.shared.b16 {%0,%1,%2,%3}, [%4];" \
        : "=r"((r)[0]), "=r"((r)[1]), "=r"((r)[2]), "=r"((r)[3]) : "r"(addr))

__device__ __forceinline__ void mma_bf16(float* d, const uint32_t* a,
                                         uint32_t b0, uint32_t b1) {
    asm volatile(
        "mma.sync.aligned.m16n8k16.row.col.f32.bf16.bf16.f32 "
        "{%0,%1,%2,%3}, {%4,%5,%6,%7}, {%8,%9}, {%0,%1,%2,%3};"
        : "+f"(d[0]), "+f"(d[1]), "+f"(d[2]), "+f"(d[3])
        : "r"(a[0]), "r"(a[1]), "r"(a[2]), "r"(a[3]), "r"(b0), "r"(b1));
}

__device__ __forceinline__ void bf16_split(float v, bf16& h, bf16& l) {
    h = __float2bfloat16(v);
    l = __float2bfloat16(v - __bfloat162float(h));
}
__device__ __forceinline__ uint32_t pack2(bf16 a, bf16 b) {
    __nv_bfloat162 t; t.x = a; t.y = b;
    return *(uint32_t*)&t;
}

// ---------------- 1. transpose shape features -> bf16 hi/lo point-major -----
__global__ void k_transpose(const float* __restrict__ x) {
    __shared__ float t[32][33];
    int b  = blockIdx.z;
    int cB = blockIdx.x * 32;
    int nB = blockIdx.y * 32;
    int tx = threadIdx.x, ty = threadIdx.y;
    const float* xb = x + (size_t)b * XCH * NPTS;
#pragma unroll
    for (int i = ty; i < 32; i += 8)
        t[i][tx] = xb[(size_t)(HEADC + cB + i) * NPTS + nB + tx];
    __syncthreads();
    size_t base = ((size_t)b * NPTS + nB) * SHAPEC + cB;
#pragma unroll
    for (int i = ty; i < 32; i += 8) {
        float v = t[tx][i];
        bf16 h, l; bf16_split(v, h, l);
        g_xhi[base + (size_t)i * SHAPEC + tx] = h;
        g_xlo[base + (size_t)i * SHAPEC + tx] = l;
    }
}

// ---------------- 2. head channels + zero pad into a0 (bf16 hi/lo) ----------
__global__ void k_head(const float* __restrict__ x) {
    int i = blockIdx.x * 256 + threadIdx.x;     // 8192 * 32
    int p = i >> 5, s = i & 31;
    float v = 0.f;
    int col;
    if (s < 8) {
        int b = p >> 10, n = p & 1023;
        v = x[(size_t)b * XCH * NPTS + (size_t)s * NPTS + n];
        col = s;
    } else {
        col = 128 + s;                           // 136..159 pad
    }
    bf16 h, l; bf16_split(v, h, l);
    g_a0hi[(size_t)p * K0PAD + col] = h;
    g_a0lo[(size_t)p * K0PAD + col] = l;
}

// ---------------- 3a. conv weight split+pad: W[C,Kin] -> hi/lo [C,Kpad] ------
__global__ void k_wsplit(const float* __restrict__ w, bf16* __restrict__ hi,
                         bf16* __restrict__ lo, int Kin, int Kpad, int total) {
    int i = blockIdx.x * 256 + threadIdx.x;
    if (i >= total) return;
    int c = i / Kpad, k = i - c * Kpad;
    float v = (k < Kin) ? w[(size_t)c * Kin + k] : 0.f;
    bf16 h, l; bf16_split(v, h, l);
    hi[i] = h;
    lo[i] = l;
}

// ---------------- 3b. expert weight transpose+split: [e][k][out]->[e][out][k]
__global__ void k_tsplit(const float* __restrict__ src, bf16* __restrict__ hi,
                         bf16* __restrict__ lo, int K, int OUT) {
    __shared__ float t[32][33];
    int e  = blockIdx.z;
    int k0 = blockIdx.x * 32;
    int o0 = blockIdx.y * 32;
    int tx = threadIdx.x, ty = threadIdx.y;
    const float* s = src + (size_t)e * K * OUT;
#pragma unroll
    for (int i = ty; i < 32; i += 8)
        t[i][tx] = s[(size_t)(k0 + i) * OUT + o0 + tx];
    __syncthreads();
    size_t base = (size_t)e * OUT * K + (size_t)o0 * K + k0;
#pragma unroll
    for (int i = ty; i < 32; i += 8) {
        float v = t[tx][i];
        bf16 h, l; bf16_split(v, h, l);
        hi[base + (size_t)i * K + tx] = h;
        lo[base + (size_t)i * K + tx] = l;
    }
}

// ---------------- 4. counting sort points by category (tiles of 64) ---------
__global__ void k_build(const int* __restrict__ cats) {
    __shared__ int cnt[NEXPERT];
    __shared__ int off[NEXPERT + 1];
    __shared__ int cur[NEXPERT];
    int tid = threadIdx.x;
    if (tid < NEXPERT) cnt[tid] = 0;
    __syncthreads();
    for (int i = tid; i < NPOINTS; i += blockDim.x) atomicAdd(&cnt[cats[i]], 1);
    __syncthreads();
    if (tid == 0) {
        int s = 0;
        for (int e = 0; e < NEXPERT; e++) { off[e] = s; s += cnt[e]; }
        off[NEXPERT] = s;
        int t = 0;
        for (int e = 0; e < NEXPERT; e++)
            for (int st = off[e]; st < off[e + 1]; st += ETILE) {
                g_tileExpert[t] = e;
                g_tileStart[t]  = st;
                g_tileLen[t]    = min(ETILE, off[e + 1] - st);
                t++;
            }
        g_nTiles = t;
    }
    __syncthreads();
    if (tid < NEXPERT) cur[tid] = off[tid];
    __syncthreads();
    for (int i = tid; i < NPOINTS; i += blockDim.x) {
        int pos = atomicAdd(&cur[cats[i]], 1);
        g_idx[pos] = i;
    }
}

// ---------------- 5. fused expert MLP on tensor cores ----------------
// Per tile: 64 points, one expert. Stage1: h=relu(A@W1+b1) kept in smem
// (bf16 hi/lo, ldmatrix layout). Stage2: o=h@W2+b2 scattered to g_a0.
// smem: A(10240) B(40960) H(81920) = 133120 B.
#define ESM_A  0
#define ESM_B  10240
#define ESM_H  51200
#define ESMEM  133120

__global__ void __launch_bounds__(256) k_expert_mma(
    const float* __restrict__ b1g, const float* __restrict__ b2g)
{
    int t = blockIdx.x;
    if (t >= g_nTiles) return;
    int e = g_tileExpert[t], start = g_tileStart[t], len = g_tileLen[t];

    extern __shared__ char smraw[];
    __shared__ int pidx[ETILE];
    __shared__ int gidx[ETILE];

    int tid = threadIdx.x, lane = tid & 31, wid = tid >> 5;
    uint32_t sb = smem_u32(smraw);

    if (tid < ETILE) {
        int pi = (tid < len) ? g_idx[start + tid] : -1;
        pidx[tid] = pi;
        gidx[tid] = pi < 0 ? 0 : pi;
    }
    __syncthreads();

    // ======== stage 1: h[64,256] = relu(A[64,256] @ W1T[256,256]^T + b1) ====
    // warp layout: 1 x 8 (each warp: all 64 rows x 32 cols)
    {
        float acc[4][4][4];
#pragma unroll
        for (int a = 0; a < 4; a++)
#pragma unroll
            for (int b = 0; b < 4; b++)
#pragma unroll
                for (int c = 0; c < 4; c++) acc[a][b][c] = 0.f;

        const bf16* w1h = g_e1hi + (size_t)e * SC_HID * SHAPEC;
        const bf16* w1l = g_e1lo + (size_t)e * SC_HID * SHAPEC;

        uint32_t rowA = (uint32_t)(lane & 15) * 80 + (lane >> 4) * 16;
        uint32_t rowB = (uint32_t)(wid * 32 + (lane & 15)) * 80 + (lane >> 4) * 16;

        for (int ks = 0; ks < 8; ks++) {
            // A gather: 512 x 16B chunks
#pragma unroll
            for (int r = 0; r < 2; r++) {
                int id = tid + r * 256;
                int half = id >> 8, idx = id & 255;
                int row = idx >> 2, ch = idx & 3;
                const bf16* src = (half ? g_xlo : g_xhi)
                                + (size_t)gidx[row] * SHAPEC + ks * 32 + ch * 8;
                CP_ASYNC16(sb + ESM_A + half * 5120 + (uint32_t)row * 80 + ch * 16, src);
            }
            // B: 2048 x 16B chunks
#pragma unroll
            for (int r = 0; r < 8; r++) {
                int id = tid + r * 256;
                int half = id >> 10, idx = id & 1023;
                int row = idx >> 2, ch = idx & 3;
                const bf16* src = (half ? w1l : w1h)
                                + (size_t)row * SHAPEC + ks * 32 + ch * 8;
                CP_ASYNC16(sb + ESM_B + half * 20480 + (uint32_t)row * 80 + ch * 16, src);
            }
            CP_COMMIT();
            CP_WAIT0();
            __syncthreads();
#pragma unroll
            for (int s = 0; s < 2; s++) {
                uint32_t aH[4][4], aL[4][4], bH[2][4], bL[2][4];
#pragma unroll
                for (int mf = 0; mf < 4; mf++) {
                    uint32_t ad = sb + ESM_A + rowA + (uint32_t)mf * (16 * 80) + s * 32;
                    LDSM4(aH[mf], ad);
                    LDSM4(aL[mf], ad + 5120);
                }
#pragma unroll
                for (int p = 0; p < 2; p++) {
                    uint32_t bd = sb + ESM_B + rowB + (uint32_t)p * (16 * 80) + s * 32;
                    LDSM4(bH[p], bd);
                    LDSM4(bL[p], bd + 20480);
                }
#pragma unroll
                for (int mf = 0; mf < 4; mf++)
#pragma unroll
                    for (int nf = 0; nf < 4; nf++) {
                        int p = nf >> 1, sel = nf & 1;
                        mma_bf16(acc[mf][nf], aH[mf], bH[p][sel], bH[p][sel + 2]);
                        mma_bf16(acc[mf][nf], aH[mf], bL[p][sel], bL[p][sel + 2]);
                        mma_bf16(acc[mf][nf], aL[mf], bH[p][sel], bH[p][sel + 2]);
                    }
            }
            __syncthreads();
        }

        // epilogue1: +b1, relu, split -> smem h (ldmatrix layout, 80B rows)
        const float* b1 = b1g + e * SC_HID;
#pragma unroll
        for (int mf = 0; mf < 4; mf++) {
            int row = mf * 16 + (lane >> 2);
#pragma unroll
            for (int nf = 0; nf < 4; nf++) {
                int col = wid * 32 + nf * 8 + 2 * (lane & 3);
                float b0v = b1[col], b1v = b1[col + 1];
                float v0 = fmaxf(acc[mf][nf][0] + b0v, 0.f);
                float v1 = fmaxf(acc[mf][nf][1] + b1v, 0.f);
                float v2 = fmaxf(acc[mf][nf][2] + b0v, 0.f);
                float v3 = fmaxf(acc[mf][nf][3] + b1v, 0.f);
                int ks = col >> 5, cw = col & 31;
                uint32_t off = (uint32_t)ks * 5120 + (uint32_t)row * 80 + cw * 2;
                bf16 h0, l0, h1, l1;
                bf16_split(v0, h0, l0); bf16_split(v1, h1, l1);
                *(uint32_t*)(smraw + ESM_H + off)         = pack2(h0, h1);
                *(uint32_t*)(smraw + ESM_H + 40960 + off) = pack2(l0, l1);
                bf16_split(v2, h0, l0); bf16_split(v3, h1, l1);
                *(uint32_t*)(smraw + ESM_H + off + 8 * 80)         = pack2(h0, h1);
                *(uint32_t*)(smraw + ESM_H + 40960 + off + 8 * 80) = pack2(l0, l1);
            }
        }
    }
    __syncthreads();

    // ======== stage 2: o[64,128] = h @ W2T[128,256]^T + b2 ====
    // warp layout: 2 x 4 (warp tile 32 x 32)
    {
        int warp_m = wid & 1, warp_n = wid >> 1;
        float acc[2][4][4];
#pragma unroll
        for (int a = 0; a < 2; a++)
#pragma unroll
            for (int b = 0; b < 4; b++)
#pragma unroll
                for (int c = 0; c < 4; c++) acc[a][b][c] = 0.f;

        const bf16* w2h = g_e2hi + (size_t)e * SC_OUT * SC_HID;
        const bf16* w2l = g_e2lo + (size_t)e * SC_OUT * SC_HID;

        uint32_t rowA = (uint32_t)(warp_m * 32 + (lane & 15)) * 80 + (lane >> 4) * 16;
        uint32_t rowB = (uint32_t)(warp_n * 32 + (lane & 15)) * 80 + (lane >> 4) * 16;

        for (int ks = 0; ks < 8; ks++) {
            // B: 1024 x 16B chunks
#pragma unroll
            for (int r = 0; r < 4; r++) {
                int id = tid + r * 256;
                int half = id >> 9, idx = id & 511;
                int row = idx >> 2, ch = idx & 3;
                const bf16* src = (half ? w2l : w2h)
                                + (size_t)row * SC_HID + ks * 32 + ch * 8;
                CP_ASYNC16(sb + ESM_B + half * 20480 + (uint32_t)row * 80 + ch * 16, src);
            }
            CP_COMMIT();
            CP_WAIT0();
            __syncthreads();
            uint32_t hbase = sb + ESM_H + (uint32_t)ks * 5120;
#pragma unroll
            for (int s = 0; s < 2; s++) {
                uint32_t aH[2][4], aL[2][4], bH[2][4], bL[2][4];
#pragma unroll
                for (int mf = 0; mf < 2; mf++) {
                    uint32_t ad = hbase + rowA + (uint32_t)mf * (16 * 80) + s * 32;
                    LDSM4(aH[mf], ad);
                    LDSM4(aL[mf], ad + 40960);
                }
#pragma unroll
                for (int p = 0; p < 2; p++) {
                    uint32_t bd = sb + ESM_B + rowB + (uint32_t)p * (16 * 80) + s * 32;
                    LDSM4(bH[p], bd);
                    LDSM4(bL[p], bd + 20480);
                }
#pragma unroll
                for (int mf = 0; mf < 2; mf++)
#pragma unroll
                    for (int nf = 0; nf < 4; nf++) {
                        int p = nf >> 1, sel = nf & 1;
                        mma_bf16(acc[mf][nf], aH[mf], bH[p][sel], bH[p][sel + 2]);
                        mma_bf16(acc[mf][nf], aH[mf], bL[p][sel], bL[p][sel + 2]);
                        mma_bf16(acc[mf][nf], aL[mf], bH[p][sel], bH[p][sel + 2]);
                    }
            }
            __syncthreads();
        }

        // epilogue2: +b2, split, scatter to g_a0
        const float* b2 = b2g + e * SC_OUT;
#pragma unroll
        for (int mf = 0; mf < 2; mf++) {
            int row = warp_m * 32 + mf * 16 + (lane >> 2);
#pragma unroll
            for (int nf = 0; nf < 4; nf++) {
                int col = warp_n * 32 + nf * 8 + 2 * (lane & 3);
                float b0v = b2[col], b1v = b2[col + 1];
                float v0 = acc[mf][nf][0] + b0v, v1 = acc[mf][nf][1] + b1v;
                float v2 = acc[mf][nf][2] + b0v, v3 = acc[mf][nf][3] + b1v;
                int pi0 = pidx[row], pi1 = pidx[row + 8];
                if (pi0 >= 0) {
                    bf16 h0, l0, h1, l1;
                    bf16_split(v0, h0, l0); bf16_split(v1, h1, l1);
                    *(uint32_t*)(g_a0hi + (size_t)pi0 * K0PAD + HEADC + col) = pack2(h0, h1);
                    *(uint32_t*)(g_a0lo + (size_t)pi0 * K0PAD + HEADC + col) = pack2(l0, l1);
                }
                if (pi1 >= 0) {
                    bf16 h0, l0, h1, l1;
                    bf16_split(v2, h0, l0); bf16_split(v3, h1, l1);
                    *(uint32_t*)(g_a0hi + (size_t)pi1 * K0PAD + HEADC + col) = pack2(h0, h1);
                    *(uint32_t*)(g_a0lo + (size_t)pi1 * K0PAD + HEADC + col) = pack2(l0, l1);
                }
            }
        }
    }
}

// ---------------- 6. bf16 mma.sync GEMM (3-MMA hi/lo split) ----------------
// SPLIT=1: bf16 hi/lo outputs. SPLIT=0: fused max-pool partial -> g_part.
#define GSMEM (2 * 40960)

template <int KTOT, int RELU, int SPLIT>
__global__ void __launch_bounds__(256) gemm_mma(
    const bf16* __restrict__ aHi, const bf16* __restrict__ aLo,
    const bf16* __restrict__ wHi, const bf16* __restrict__ wLo,
    const float* __restrict__ bias,
    bf16* __restrict__ oHi, bf16* __restrict__ oLo, int KOUT)
{
    extern __shared__ char smraw[];
    const int NK = KTOT / 32;
    int tid = threadIdx.x, lane = tid & 31, wid = tid >> 5;
    int warp_m = wid & 1, warp_n = wid >> 1;     // 2 x 4 warps
    int m0 = blockIdx.x * 128, c0 = blockIdx.y * 128;

    uint32_t smBase = smem_u32(smraw);
    uint32_t rowA = (uint32_t)(warp_m * 64 + (lane & 15)) * 80 + (lane >> 4) * 16;
    uint32_t rowB = (uint32_t)(warp_n * 32 + (lane & 15)) * 80 + (lane >> 4) * 16;

    float acc[4][4][4];
#pragma unroll
    for (int a = 0; a < 4; a++)
#pragma unroll
        for (int b = 0; b < 4; b++)
#pragma unroll
            for (int c = 0; c < 4; c++) acc[a][b][c] = 0.f;

    auto loadStage = [&](int ks, int st) {
        uint32_t sbs = smBase + st * 40960;
#pragma unroll
        for (int i = 0; i < 8; i++) {
            const int blk = i >> 1;                       // 0:AH 1:AL 2:BH 3:BL
            int id = tid + (i & 1) * 256;
            int r = id >> 2, ch = id & 3;
            const bf16* src;
            if (blk == 0)      src = aHi + (size_t)(m0 + r) * KTOT;
            else if (blk == 1) src = aLo + (size_t)(m0 + r) * KTOT;
            else if (blk == 2) src = wHi + (size_t)(c0 + r) * KTOT;
            else               src = wLo + (size_t)(c0 + r) * KTOT;
            src += ks * 32 + ch * 8;
            CP_ASYNC16(sbs + blk * 10240 + (uint32_t)r * 80 + ch * 16, src);
        }
        CP_COMMIT();
    };

    loadStage(0, 0);
    for (int ks = 0; ks < NK; ks++) {
        if (ks + 1 < NK) { loadStage(ks + 1, (ks + 1) & 1); CP_WAIT1(); }
        else             { CP_WAIT0(); }
        __syncthreads();

        uint32_t sbs = smBase + (ks & 1) * 40960;
#pragma unroll
        for (int s = 0; s < 2; s++) {
            uint32_t aH[4][4], aL[4][4], bH[2][4], bL[2][4];
#pragma unroll
            for (int mf = 0; mf < 4; mf++) {
                uint32_t ad = sbs + rowA + (uint32_t)mf * (16 * 80) + s * 32;
                LDSM4(aH[mf], ad);
                LDSM4(aL[mf], ad + 10240);
            }
#pragma unroll
            for (int p = 0; p < 2; p++) {
                uint32_t bd = sbs + 20480 + rowB + (uint32_t)p * (16 * 80) + s * 32;
                LDSM4(bH[p], bd);
                LDSM4(bL[p], bd + 10240);
            }
#pragma unroll
            for (int mf = 0; mf < 4; mf++)
#pragma unroll
                for (int nf = 0; nf < 4; nf++) {
                    int p = nf >> 1, sel = nf & 1;
                    mma_bf16(acc[mf][nf], aH[mf], bH[p][sel], bH[p][sel + 2]);
                    mma_bf16(acc[mf][nf], aH[mf], bL[p][sel], bL[p][sel + 2]);
                    mma_bf16(acc[mf][nf], aL[mf], bH[p][sel], bH[p][sel + 2]);
                }
        }
        __syncthreads();
    }

    if (SPLIT) {
        // ---- epilogue: +bias, relu, bf16-split store ----
#pragma unroll
        for (int mf = 0; mf < 4; mf++) {
            int row = m0 + warp_m * 64 + mf * 16 + (lane >> 2);
#pragma unroll
            for (int nf = 0; nf < 4; nf++) {
                int col = c0 + warp_n * 32 + nf * 8 + 2 * (lane & 3);
                float b0v = bias[col], b1v = bias[col + 1];
                float v0 = acc[mf][nf][0] + b0v, v1 = acc[mf][nf][1] + b1v;
                float v2 = acc[mf][nf][2] + b0v, v3 = acc[mf][nf][3] + b1v;
                if (RELU) {
                    v0 = fmaxf(v0, 0.f); v1 = fmaxf(v1, 0.f);
                    v2 = fmaxf(v2, 0.f); v3 = fmaxf(v3, 0.f);
                }
                bf16 h0, l0, h1, l1;
                bf16_split(v0, h0, l0); bf16_split(v1, h1, l1);
                *(uint32_t*)(oHi + (size_t)row * KOUT + col) = pack2(h0, h1);
                *(uint32_t*)(oLo + (size_t)row * KOUT + col) = pack2(l0, l1);
                bf16_split(v2, h0, l0); bf16_split(v3, h1, l1);
                *(uint32_t*)(oHi + (size_t)(row + 8) * KOUT + col) = pack2(h0, h1);
                *(uint32_t*)(oLo + (size_t)(row + 8) * KOUT + col) = pack2(l0, l1);
            }
        }
    } else {
        // ---- fused max-pool epilogue: partial max over 128 rows ----
        float* pm = (float*)smraw;   // [2][128]
#pragma unroll
        for (int nf = 0; nf < 4; nf++) {
            float c0m = -FLT_MAX, c1m = -FLT_MAX;
#pragma unroll
            for (int mf = 0; mf < 4; mf++) {
                int col = c0 + warp_n * 32 + nf * 8 + 2 * (lane & 3);
                float b0v = bias[col], b1v = bias[col + 1];
                c0m = fmaxf(c0m, fmaxf(acc[mf][nf][0] + b0v, acc[mf][nf][2] + b0v));
                c1m = fmaxf(c1m, fmaxf(acc[mf][nf][1] + b1v, acc[mf][nf][3] + b1v));
            }
#pragma unroll
            for (int o = 4; o < 32; o <<= 1) {
                c0m = fmaxf(c0m, __shfl_xor_sync(0xFFFFFFFFu, c0m, o));
                c1m = fmaxf(c1m, __shfl_xor_sync(0xFFFFFFFFu, c1m, o));
            }
            if (lane < 4) {
                int cc = warp_n * 32 + nf * 8 + 2 * lane;
                pm[warp_m * 128 + cc]     = c0m;
                pm[warp_m * 128 + cc + 1] = c1m;
            }
        }
        __syncthreads();
        if (tid < 64) {
            int cc = tid * 2;
            float m0v = fmaxf(pm[cc],     pm[128 + cc]);
            float m1v = fmaxf(pm[cc + 1], pm[128 + cc + 1]);
            int b = m0 >> 10, part = (m0 >> 7) & 7;
            *(float2*)(g_part + (size_t)(b * 8 + part) * C3OUT + c0 + cc)
                = make_float2(m0v, m1v);
        }
    }
}

// ---------------- 7. max pool final stage ----------------
__global__ void k_poolB(float* __restrict__ extra, int we) {
    int i = blockIdx.x * 256 + threadIdx.x;   // 8192
    float m = -FLT_MAX;
    int b = i >> 10, c = i & 1023;
#pragma unroll
    for (int part = 0; part < 8; part++)
        m = fmaxf(m, g_part[(b * 8 + part) * C3OUT + c]);
    g_lat[i] = m;
    if (we) extra[i] = m;
}

// ---------------- 8. decoder MLP ----------------
template <int RELU>
__global__ void __launch_bounds__(256) mlp8(
    const float* __restrict__ A, const float* __restrict__ W,
    const float* __restrict__ bias, float* __restrict__ Out,
    int K, int N)
{
    extern __shared__ float Ash[];
    __shared__ float red[256 * 8];
    int tid = threadIdx.x;
    for (int i = tid; i < 8 * K / 4; i += 256)
        ((float4*)Ash)[i] = ((const float4*)A)[i];
    __syncthreads();

    int col   = blockIdx.x * 64 + (tid & 63);
    int slice = tid >> 6;
    int kPer  = K >> 2;
    int k0    = slice * kPer;

    float acc[8];
#pragma unroll
    for (int bb = 0; bb < 8; bb++) acc[bb] = 0.f;

    for (int k = k0; k < k0 + kPer; k += 4) {
        float w0 = W[(size_t)(k + 0) * N + col];
        float w1 = W[(size_t)(k + 1) * N + col];
        float w2 = W[(size_t)(k + 2) * N + col];
        float w3 = W[(size_t)(k + 3) * N + col];
#pragma unroll
        for (int bb = 0; bb < 8; bb++) {
            float4 a4 = ((const float4*)(Ash + bb * K))[k >> 2];
            acc[bb] = fmaf(a4.x, w0, acc[bb]);
            acc[bb] = fmaf(a4.y, w1, acc[bb]);
            acc[bb] = fmaf(a4.z, w2, acc[bb]);
            acc[bb] = fmaf(a4.w, w3, acc[bb]);
        }
    }
#pragma unroll
    for (int bb = 0; bb < 8; bb++) red[tid * 8 + bb] = acc[bb];
    __syncthreads();
    if (slice == 0) {
        float bsv = bias[col];
#pragma unroll
        for (int bb = 0; bb < 8; bb++) {
            float v = red[tid * 8 + bb] + red[(tid + 64) * 8 + bb]
                    + red[(tid + 128) * 8 + bb] + red[(tid + 192) * 8 + bb] + bsv;
            if (RELU) v = fmaxf(v, 0.f);
            Out[(size_t)bb * N + col] = v;
        }
    }
}

// ---------------- launch ----------------
extern "C" void kernel_launch(void* const* d_in, const int* in_sizes, int n_in,
                              void* d_out, int out_size) {
    const float* x    = (const float*)d_in[0];
    const int*   cats = (const int*)  d_in[1];
    const float* W1   = (const float*)d_in[2];
    const float* b1   = (const float*)d_in[3];
    const float* W2   = (const float*)d_in[4];
    const float* b2   = (const float*)d_in[5];
    const float* Wc1  = (const float*)d_in[6];
    const float* bc1  = (const float*)d_in[7];
    const float* Wc2  = (const float*)d_in[8];
    const float* bc2  = (const float*)d_in[9];
    const float* Wc3  = (const float*)d_in[10];
    const float* bc3  = (const float*)d_in[11];
    const float* Wd1  = (const float*)d_in[12];
    const float* bd1  = (const float*)d_in[13];
    const float* Wd2  = (const float*)d_in[14];
    const float* bd2  = (const float*)d_in[15];
    const float* Wd3  = (const float*)d_in[16];
    const float* bd3  = (const float*)d_in[17];
    float* out = (float*)d_out;

    cudaFuncSetAttribute(k_expert_mma, cudaFuncAttributeMaxDynamicSharedMemorySize, ESMEM);
    cudaFuncSetAttribute(mlp8<1>,  cudaFuncAttributeMaxDynamicSharedMemorySize, 65536);
    cudaFuncSetAttribute(mlp8<0>,  cudaFuncAttributeMaxDynamicSharedMemorySize, 65536);
    cudaFuncSetAttribute(gemm_mma<K0PAD, 1, 1>, cudaFuncAttributeMaxDynamicSharedMemorySize, GSMEM);
    cudaFuncSetAttribute(gemm_mma<C1OUT, 1, 1>, cudaFuncAttributeMaxDynamicSharedMemorySize, GSMEM);
    cudaFuncSetAttribute(gemm_mma<C2OUT, 0, 0>, cudaFuncAttributeMaxDynamicSharedMemorySize, GSMEM);

    bf16 *p_a0h, *p_a0l, *p_a1h, *p_a1l, *p_a2h, *p_a2l;
    bf16 *p_w1h, *p_w1l, *p_w2h, *p_w2l, *p_w3h, *p_w3l;
    bf16 *p_e1h, *p_e1l, *p_e2h, *p_e2l;
    float *p_lat, *p_d1, *p_d2;
    cudaGetSymbolAddress((void**)&p_a0h, g_a0hi);
    cudaGetSymbolAddress((void**)&p_a0l, g_a0lo);
    cudaGetSymbolAddress((void**)&p_a1h, g_a1hi);
    cudaGetSymbolAddress((void**)&p_a1l, g_a1lo);
    cudaGetSymbolAddress((void**)&p_a2h, g_a2hi);
    cudaGetSymbolAddress((void**)&p_a2l, g_a2lo);
    cudaGetSymbolAddress((void**)&p_w1h, g_w1hi);
    cudaGetSymbolAddress((void**)&p_w1l, g_w1lo);
    cudaGetSymbolAddress((void**)&p_w2h, g_w2hi);
    cudaGetSymbolAddress((void**)&p_w2l, g_w2lo);
    cudaGetSymbolAddress((void**)&p_w3h, g_w3hi);
    cudaGetSymbolAddress((void**)&p_w3l, g_w3lo);
    cudaGetSymbolAddress((void**)&p_e1h, g_e1hi);
    cudaGetSymbolAddress((void**)&p_e1l, g_e1lo);
    cudaGetSymbolAddress((void**)&p_e2h, g_e2hi);
    cudaGetSymbolAddress((void**)&p_e2l, g_e2lo);
    cudaGetSymbolAddress((void**)&p_lat, g_lat);
    cudaGetSymbolAddress((void**)&p_d1,  g_d1);
    cudaGetSymbolAddress((void**)&p_d2,  g_d2);

    // feature prep
    k_transpose<<<dim3(SHAPEC / 32, NPTS / 32, BATCH), dim3(32, 8)>>>(x);
    k_head<<<(NPOINTS * 32) / 256, 256>>>(x);
    k_wsplit<<<(C1OUT * K0PAD + 255) / 256, 256>>>(Wc1, p_w1h, p_w1l, 136, K0PAD, C1OUT * K0PAD);
    k_wsplit<<<(C2OUT * C1OUT + 255) / 256, 256>>>(Wc2, p_w2h, p_w2l, C1OUT, C1OUT, C2OUT * C1OUT);
    k_wsplit<<<(C3OUT * C2OUT + 255) / 256, 256>>>(Wc3, p_w3h, p_w3l, C2OUT, C2OUT, C3OUT * C2OUT);
    k_tsplit<<<dim3(SHAPEC / 32, SC_HID / 32, NEXPERT), dim3(32, 8)>>>(W1, p_e1h, p_e1l, SHAPEC, SC_HID);
    k_tsplit<<<dim3(SC_HID / 32, SC_OUT / 32, NEXPERT), dim3(32, 8)>>>(W2, p_e2h, p_e2l, SC_HID, SC_OUT);

    // expert routing + fused MoE on tensor cores
    k_build<<<1, 256>>>(cats);
    k_expert_mma<<<MAXTILES, 256, ESMEM>>>(b1, b2);

    // conv stack on tensor cores (layer 3 fuses the max-pool partial)
    gemm_mma<K0PAD, 1, 1><<<dim3(64, C1OUT / 128), 256, GSMEM>>>(
        p_a0h, p_a0l, p_w1h, p_w1l, bc1, p_a1h, p_a1l, C1OUT);
    gemm_mma<C1OUT, 1, 1><<<dim3(64, C2OUT / 128), 256, GSMEM>>>(
        p_a1h, p_a1l, p_w2h, p_w2l, bc2, p_a2h, p_a2l, C2OUT);
    gemm_mma<C2OUT, 0, 0><<<dim3(64, C3OUT / 128), 256, GSMEM>>>(
        p_a2h, p_a2l, p_w3h, p_w3l, bc3, (bf16*)0, (bf16*)0, C3OUT);

    // max pool final + latent
    int write_extra = (out_size >= 65536 + 8192) ? 1 : 0;
    k_poolB<<<NPOINTS / 256, 256>>>(out + 65536, write_extra);

    // decoder MLP
    mlp8<1><<<DEC1 / 64, 256, 8 * DEC1 * 4>>>(p_lat, Wd1, bd1, p_d1, DEC1, DEC1);
    mlp8<1><<<DEC2 / 64, 256, 8 * DEC1 * 4>>>(p_d1,  Wd2, bd2, p_d2, DEC1, DEC2);
    mlp8<0><<<DEC3 / 64, 256, 8 * DEC2 * 4>>>(p_d2,  Wd3, bd3, out,  DEC2, DEC3);
}